// round 2
// baseline (speedup 1.0000x reference)
#include <cuda_runtime.h>
#include <cuda_bf16.h>
#include <math.h>

// ----------------------------------------------------------------------------
// Problem constants
// ----------------------------------------------------------------------------
#define D_MODEL   2048
#define NUM_HEADS 16
#define D_K       128
#define HALF_DK   64
#define BATCH     2
#define SEQ       2048
#define M_ROWS    (BATCH * SEQ)          // 4096

// ----------------------------------------------------------------------------
// Scratch (device globals; no allocation allowed). Kernels reference these
// directly — no cudaGetSymbolAddress in the launcher.
// ----------------------------------------------------------------------------
__device__ float g_Q  [M_ROWS * D_MODEL];
__device__ float g_K  [M_ROWS * D_MODEL];
__device__ float g_V  [M_ROWS * D_MODEL];
__device__ float g_ctx[M_ROWS * D_MODEL];

// ----------------------------------------------------------------------------
// GEMM: C[M,N] = A[M,K] * B[N,K]^T   (both row-major, K contiguous -> NT form)
// 128x128 block tile, BK=8, 256 threads, 8x8 per-thread microtile.
// ----------------------------------------------------------------------------
#define GBM 128
#define GBN 128
#define GBK 8

__device__ __forceinline__
void gemm_nt_body(const float* __restrict__ A, const float* __restrict__ B,
                  float* __restrict__ C, int K, int N,
                  int bx, int by, int tid)
{
    __shared__ float As[GBK][GBM];
    __shared__ float Bs[GBK][GBN];

    const int tr = tid >> 4;     // 0..15
    const int tc = tid & 15;     // 0..15

    float acc[8][8];
#pragma unroll
    for (int i = 0; i < 8; i++)
#pragma unroll
        for (int j = 0; j < 8; j++) acc[i][j] = 0.0f;

    const float* Ab = A + (size_t)by * GBM * K;
    const float* Bb = B + (size_t)bx * GBN * K;

    const int lrow = tid >> 1;          // 0..127
    const int lk   = (tid & 1) * 4;     // 0 or 4

    for (int k0 = 0; k0 < K; k0 += GBK) {
        float4 av = *(const float4*)(Ab + (size_t)lrow * K + k0 + lk);
        float4 bv = *(const float4*)(Bb + (size_t)lrow * K + k0 + lk);
        As[lk + 0][lrow] = av.x; As[lk + 1][lrow] = av.y;
        As[lk + 2][lrow] = av.z; As[lk + 3][lrow] = av.w;
        Bs[lk + 0][lrow] = bv.x; Bs[lk + 1][lrow] = bv.y;
        Bs[lk + 2][lrow] = bv.z; Bs[lk + 3][lrow] = bv.w;
        __syncthreads();

#pragma unroll
        for (int kk = 0; kk < GBK; kk++) {
            float ra[8], rb[8];
            *(float4*)&ra[0] = *(const float4*)&As[kk][tr * 8];
            *(float4*)&ra[4] = *(const float4*)&As[kk][tr * 8 + 4];
            *(float4*)&rb[0] = *(const float4*)&Bs[kk][tc * 8];
            *(float4*)&rb[4] = *(const float4*)&Bs[kk][tc * 8 + 4];
#pragma unroll
            for (int i = 0; i < 8; i++)
#pragma unroll
                for (int j = 0; j < 8; j++)
                    acc[i][j] = fmaf(ra[i], rb[j], acc[i][j]);
        }
        __syncthreads();
    }

    float* Cb = C + (size_t)(by * GBM) * N + bx * GBN;
#pragma unroll
    for (int i = 0; i < 8; i++) {
        float* crow = Cb + (size_t)(tr * 8 + i) * N + tc * 8;
        *(float4*)(crow)     = *(const float4*)&acc[i][0];
        *(float4*)(crow + 4) = *(const float4*)&acc[i][4];
    }
}

// Fused QKV projection: grid.z in {0,1,2} selects (Wq->g_Q, Wk->g_K, Wv->g_V).
__global__ __launch_bounds__(256, 2)
void qkv_proj_kernel(const float* __restrict__ x,
                     const float* __restrict__ Wq,
                     const float* __restrict__ Wk,
                     const float* __restrict__ Wv)
{
    const float* W;
    float* C;
    switch (blockIdx.z) {
        case 0:  W = Wq; C = g_Q; break;
        case 1:  W = Wk; C = g_K; break;
        default: W = Wv; C = g_V; break;
    }
    gemm_nt_body(x, W, C, D_MODEL, D_MODEL, blockIdx.x, blockIdx.y, threadIdx.x);
}

// Output projection: out = g_ctx @ Wo^T
__global__ __launch_bounds__(256, 2)
void out_proj_kernel(const float* __restrict__ Wo, float* __restrict__ out)
{
    gemm_nt_body(g_ctx, Wo, out, D_MODEL, D_MODEL, blockIdx.x, blockIdx.y, threadIdx.x);
}

// ----------------------------------------------------------------------------
// RoPE (interleaved pairs) applied in-place to g_Q and g_K.
// Angles in fp64: positions go up to 2047 rad; fp32 trig would eat the budget.
// ----------------------------------------------------------------------------
__global__ void rope_kernel(const int* __restrict__ pos)
{
    int idx = blockIdx.x * blockDim.x + threadIdx.x;
    const int total = M_ROWS * NUM_HEADS * HALF_DK;
    if (idx >= total) return;

    int i = idx % HALF_DK;
    int h = (idx / HALF_DK) % NUM_HEADS;
    int m = idx / (HALF_DK * NUM_HEADS);      // b*SEQ + s

    double p = (double)pos[m];
    double inv = pow(10000.0, -(double)i / 64.0);   // theta^(-2i/d_k)
    double ang = p * inv;
    float c = (float)cos(ang);
    float s = (float)sin(ang);

    size_t base = (size_t)m * D_MODEL + h * D_K + 2 * i;

    float q1 = g_Q[base], q2 = g_Q[base + 1];
    g_Q[base]     = q1 * c - q2 * s;
    g_Q[base + 1] = q1 * s + q2 * c;

    float k1 = g_K[base], k2 = g_K[base + 1];
    g_K[base]     = k1 * c - k2 * s;
    g_K[base + 1] = k1 * s + k2 * c;
}

// ----------------------------------------------------------------------------
// Flash attention, fp32, causal. Br=Bc=64, 256 threads.
// grid.x = SEQ/64 q-tiles, grid.y = BATCH*NUM_HEADS.
// smem: Qs[64][128] + Ks[64][132] + Vs[64][128] + Ps[64][65]  (~113 KB dynamic)
// ----------------------------------------------------------------------------
#define KS_STRIDE 132
#define PS_STRIDE 65
#define ATTN_SMEM_FLOATS (64*128 + 64*KS_STRIDE + 64*128 + 64*PS_STRIDE)
#define ATTN_SMEM_BYTES  (ATTN_SMEM_FLOATS * 4)

__global__ __launch_bounds__(256, 1)
void attn_kernel()
{
    extern __shared__ float sm[];
    float* Qs = sm;                       // [64][128]
    float* Ks = Qs + 64 * 128;            // [64][132]
    float* Vs = Ks + 64 * KS_STRIDE;      // [64][128]
    float* Ps = Vs + 64 * 128;            // [64][65]

    const int qt  = blockIdx.x;
    const int bh  = blockIdx.y;
    const int b   = bh >> 4;
    const int h   = bh & 15;
    const int tid = threadIdx.x;
    const int tr  = tid >> 4;             // 0..15 -> rows tr*4..tr*4+3
    const int tc  = tid & 15;             // 0..15 -> keys tc+16j / cols tc*8..

    const float scale = 0.08838834764831845f;   // 1/sqrt(128)

    const size_t rowst = D_MODEL;
    const float* Qg = g_Q + ((size_t)b * SEQ + qt * 64) * rowst + h * D_K;

    // Load Q tile, pre-scaled
    for (int t = tid; t < 64 * 32; t += 256) {
        int r = t >> 5, c4 = (t & 31) * 4;
        float4 v = *(const float4*)(Qg + (size_t)r * rowst + c4);
        v.x *= scale; v.y *= scale; v.z *= scale; v.w *= scale;
        *(float4*)&Qs[r * 128 + c4] = v;
    }

    float m_i[4], l_i[4], o[4][8];
#pragma unroll
    for (int i = 0; i < 4; i++) {
        m_i[i] = -1e30f; l_i[i] = 0.0f;
#pragma unroll
        for (int c = 0; c < 8; c++) o[i][c] = 0.0f;
    }
    __syncthreads();

    for (int j = 0; j <= qt; j++) {
        const float* Kg = g_K + ((size_t)b * SEQ + j * 64) * rowst + h * D_K;
        const float* Vg = g_V + ((size_t)b * SEQ + j * 64) * rowst + h * D_K;
        for (int t = tid; t < 64 * 32; t += 256) {
            int r = t >> 5, c4 = (t & 31) * 4;
            *(float4*)&Ks[r * KS_STRIDE + c4] = *(const float4*)(Kg + (size_t)r * rowst + c4);
            *(float4*)&Vs[r * 128 + c4]       = *(const float4*)(Vg + (size_t)r * rowst + c4);
        }
        __syncthreads();

        // scores: rows r=tr*4+i, keys kk=tc+16*jj
        float s[4][4];
#pragma unroll
        for (int i = 0; i < 4; i++)
#pragma unroll
            for (int jj = 0; jj < 4; jj++) s[i][jj] = 0.0f;

        for (int d = 0; d < 128; d++) {
            float qv[4], kv[4];
#pragma unroll
            for (int i = 0; i < 4; i++)  qv[i]  = Qs[(tr * 4 + i) * 128 + d];
#pragma unroll
            for (int jj = 0; jj < 4; jj++) kv[jj] = Ks[(tc + 16 * jj) * KS_STRIDE + d];
#pragma unroll
            for (int i = 0; i < 4; i++)
#pragma unroll
                for (int jj = 0; jj < 4; jj++)
                    s[i][jj] = fmaf(qv[i], kv[jj], s[i][jj]);
        }

        // causal mask (only diagonal tile)
        if (j == qt) {
#pragma unroll
            for (int i = 0; i < 4; i++) {
                int r = tr * 4 + i;
#pragma unroll
                for (int jj = 0; jj < 4; jj++) {
                    int kk = tc + 16 * jj;
                    if (kk > r) s[i][jj] = -1e30f;
                }
            }
        }

        // online softmax per row; the 16 threads of a row are a contiguous
        // 16-lane group -> width-16 shuffle reductions
#pragma unroll
        for (int i = 0; i < 4; i++) {
            float mloc = s[i][0];
#pragma unroll
            for (int jj = 1; jj < 4; jj++) mloc = fmaxf(mloc, s[i][jj]);
#pragma unroll
            for (int off = 8; off > 0; off >>= 1)
                mloc = fmaxf(mloc, __shfl_xor_sync(0xffffffffu, mloc, off, 16));
            float mnew  = fmaxf(m_i[i], mloc);
            float alpha = __expf(m_i[i] - mnew);

            float psum = 0.0f;
#pragma unroll
            for (int jj = 0; jj < 4; jj++) {
                float p = __expf(s[i][jj] - mnew);
                Ps[(tr * 4 + i) * PS_STRIDE + tc + 16 * jj] = p;
                psum += p;
            }
#pragma unroll
            for (int off = 8; off > 0; off >>= 1)
                psum += __shfl_xor_sync(0xffffffffu, psum, off, 16);

            l_i[i] = l_i[i] * alpha + psum;
            m_i[i] = mnew;
#pragma unroll
            for (int c = 0; c < 8; c++) o[i][c] *= alpha;
        }
        __syncthreads();   // Ps fully written before PV reads

        // PV: O[r][c] += Ps[r][k] * Vs[k][c]
        for (int kk = 0; kk < 64; kk++) {
            float pv[4];
#pragma unroll
            for (int i = 0; i < 4; i++) pv[i] = Ps[(tr * 4 + i) * PS_STRIDE + kk];
            float4 v0 = *(const float4*)&Vs[kk * 128 + tc * 8];
            float4 v1 = *(const float4*)&Vs[kk * 128 + tc * 8 + 4];
#pragma unroll
            for (int i = 0; i < 4; i++) {
                o[i][0] = fmaf(pv[i], v0.x, o[i][0]);
                o[i][1] = fmaf(pv[i], v0.y, o[i][1]);
                o[i][2] = fmaf(pv[i], v0.z, o[i][2]);
                o[i][3] = fmaf(pv[i], v0.w, o[i][3]);
                o[i][4] = fmaf(pv[i], v1.x, o[i][4]);
                o[i][5] = fmaf(pv[i], v1.y, o[i][5]);
                o[i][6] = fmaf(pv[i], v1.z, o[i][6]);
                o[i][7] = fmaf(pv[i], v1.w, o[i][7]);
            }
        }
        __syncthreads();   // before next tile overwrites Ks/Vs/Ps
    }

    float* Og = g_ctx + ((size_t)b * SEQ + qt * 64) * rowst + h * D_K;
#pragma unroll
    for (int i = 0; i < 4; i++) {
        int r = tr * 4 + i;
        float inv_l = 1.0f / l_i[i];
        float4 w0, w1;
        w0.x = o[i][0] * inv_l; w0.y = o[i][1] * inv_l;
        w0.z = o[i][2] * inv_l; w0.w = o[i][3] * inv_l;
        w1.x = o[i][4] * inv_l; w1.y = o[i][5] * inv_l;
        w1.z = o[i][6] * inv_l; w1.w = o[i][7] * inv_l;
        *(float4*)(Og + (size_t)r * rowst + tc * 8)     = w0;
        *(float4*)(Og + (size_t)r * rowst + tc * 8 + 4) = w1;
    }
}

// ----------------------------------------------------------------------------
// Launcher — kernel launches + one cudaFuncSetAttribute only.
// ----------------------------------------------------------------------------
extern "C" void kernel_launch(void* const* d_in, const int* in_sizes, int n_in,
                              void* d_out, int out_size)
{
    const float* x   = (const float*)d_in[0];
    const int*   pos = (const int*)d_in[1];
    const float* Wq  = (const float*)d_in[2];
    const float* Wk  = (const float*)d_in[3];
    const float* Wv  = (const float*)d_in[4];
    const float* Wo  = (const float*)d_in[5];
    float* out = (float*)d_out;

    dim3 gthr(256);
    dim3 qkv_grid(D_MODEL / GBN, M_ROWS / GBM, 3);   // (16, 32, 3)
    qkv_proj_kernel<<<qkv_grid, gthr>>>(x, Wq, Wk, Wv);

    {
        int total = M_ROWS * NUM_HEADS * HALF_DK;
        rope_kernel<<<(total + 255) / 256, 256>>>(pos);
    }

    cudaFuncSetAttribute(attn_kernel, cudaFuncAttributeMaxDynamicSharedMemorySize,
                         ATTN_SMEM_BYTES);
    attn_kernel<<<dim3(SEQ / 64, BATCH * NUM_HEADS), 256, ATTN_SMEM_BYTES>>>();

    dim3 ogrid(D_MODEL / GBN, M_ROWS / GBM);         // (16, 32)
    out_proj_kernel<<<ogrid, gthr>>>(Wo, out);
}

// round 4
// speedup vs baseline: 1.6307x; 1.6307x over previous
#include <cuda_runtime.h>
#include <cuda_bf16.h>
#include <math.h>
#include <stdint.h>

// ----------------------------------------------------------------------------
// Problem constants
// ----------------------------------------------------------------------------
#define D_MODEL   2048
#define NUM_HEADS 16
#define D_K       128
#define HALF_DK   64
#define BATCH     2
#define SEQ       2048
#define M_ROWS    (BATCH * SEQ)          // 4096

// ----------------------------------------------------------------------------
// Scratch (device globals)
// ----------------------------------------------------------------------------
__device__ float g_Q  [M_ROWS * D_MODEL];
__device__ float g_K  [M_ROWS * D_MODEL];
__device__ float g_V  [M_ROWS * D_MODEL];
__device__ float g_ctx[M_ROWS * D_MODEL];

// ----------------------------------------------------------------------------
// Tensor-core GEMM: C[M,N] = A[M,K] * B[N,K]^T, fp32 in/out.
// Split-bf16 3-term: A=Ah+Al, B=Bh+Bl; C += Ah*Bh + Ah*Bl + Al*Bh (fp32 acc).
// Block tile 128x128, BK=32, 256 threads (8 warps as 2Mx4N), warp tile 64x32.
// ----------------------------------------------------------------------------
#define BM 128
#define BN 128
#define BKT 32
#define SSTR 40   // bf16 row stride: 80B -> 16B-aligned rows, conflict-free ldmatrix

__device__ __forceinline__ void ldsm_x4(uint32_t* r, uint32_t addr) {
    asm volatile("ldmatrix.sync.aligned.m8n8.x4.shared.b16 {%0,%1,%2,%3}, [%4];"
                 : "=r"(r[0]), "=r"(r[1]), "=r"(r[2]), "=r"(r[3]) : "r"(addr));
}

__device__ __forceinline__ void mma16816(float* c, const uint32_t* a, const uint32_t* b) {
    asm volatile("mma.sync.aligned.m16n8k16.row.col.f32.bf16.bf16.f32 "
                 "{%0,%1,%2,%3},{%4,%5,%6,%7},{%8,%9},{%0,%1,%2,%3};"
                 : "+f"(c[0]), "+f"(c[1]), "+f"(c[2]), "+f"(c[3])
                 : "r"(a[0]), "r"(a[1]), "r"(a[2]), "r"(a[3]), "r"(b[0]), "r"(b[1]));
}

__device__ __forceinline__
void gemm_tc_body(const float* __restrict__ A, const float* __restrict__ B,
                  float* __restrict__ C, int bx, int by)
{
    __shared__ __nv_bfloat16 sAh[BM * SSTR];
    __shared__ __nv_bfloat16 sAl[BM * SSTR];
    __shared__ __nv_bfloat16 sBh[BM * SSTR];
    __shared__ __nv_bfloat16 sBl[BM * SSTR];

    const int tid  = threadIdx.x;
    const int wid  = tid >> 5;
    const int lane = tid & 31;
    const int wm   = (wid >> 2) * 64;      // warp M offset (0 or 64)
    const int wn   = (wid & 3) * 32;       // warp N offset (0,32,64,96)

    const int K = D_MODEL, N = D_MODEL;

    float acc[4][4][4];
#pragma unroll
    for (int mi = 0; mi < 4; mi++)
#pragma unroll
        for (int ni = 0; ni < 4; ni++)
#pragma unroll
            for (int e = 0; e < 4; e++) acc[mi][ni][e] = 0.0f;

    const float* Ab = A + (size_t)(by * BM) * K;
    const float* Bb = B + (size_t)(bx * BN) * K;

    // loader mapping: thread -> row tid/2, 16 consecutive cols at (tid&1)*16
    const int lr = tid >> 1;
    const int lc = (tid & 1) * 16;

    // ldmatrix base addresses (byte offsets added per k-step)
    uint32_t bAh = (uint32_t)__cvta_generic_to_shared(sAh);
    uint32_t bAl = (uint32_t)__cvta_generic_to_shared(sAl);
    uint32_t bBh = (uint32_t)__cvta_generic_to_shared(sBh);
    uint32_t bBl = (uint32_t)__cvta_generic_to_shared(sBl);

    // A frag addr: row = wm + mi*16 + (lane&15), koff = (lane>>4)*8
    uint32_t aAoff[4];
#pragma unroll
    for (int mi = 0; mi < 4; mi++) {
        int row  = wm + mi * 16 + (lane & 15);
        int koff = (lane >> 4) * 8;
        aAoff[mi] = (uint32_t)((row * SSTR + koff) * 2);
    }
    // B frag addr (x4 covers 2 n-tiles): g = lane>>3;
    // row = wn + p*16 + (g>>1)*8 + (lane&7), koff = (g&1)*8
    uint32_t aBoff[2];
#pragma unroll
    for (int p = 0; p < 2; p++) {
        int g    = lane >> 3;
        int row  = wn + p * 16 + (g >> 1) * 8 + (lane & 7);
        int koff = (g & 1) * 8;
        aBoff[p] = (uint32_t)((row * SSTR + koff) * 2);
    }

    for (int k0 = 0; k0 < K; k0 += BKT) {
        // ---- load fp32 tiles, convert to hi/lo bf16, store to smem ----
        const float* Ap = Ab + (size_t)lr * K + k0 + lc;
        const float* Bp = Bb + (size_t)lr * K + k0 + lc;
#pragma unroll
        for (int q = 0; q < 4; q++) {
            float4 av = *(const float4*)(Ap + q * 4);
            float4 bv = *(const float4*)(Bp + q * 4);
            float ax[4] = {av.x, av.y, av.z, av.w};
            float bxv[4] = {bv.x, bv.y, bv.z, bv.w};
#pragma unroll
            for (int e = 0; e < 4; e += 2) {
                __nv_bfloat16 h0 = __float2bfloat16(ax[e]);
                __nv_bfloat16 h1 = __float2bfloat16(ax[e + 1]);
                __nv_bfloat16 l0 = __float2bfloat16(ax[e]     - __bfloat162float(h0));
                __nv_bfloat16 l1 = __float2bfloat16(ax[e + 1] - __bfloat162float(h1));
                int idx = lr * SSTR + lc + q * 4 + e;
                *(__nv_bfloat162*)&sAh[idx] = __nv_bfloat162(h0, h1);
                *(__nv_bfloat162*)&sAl[idx] = __nv_bfloat162(l0, l1);
                __nv_bfloat16 H0 = __float2bfloat16(bxv[e]);
                __nv_bfloat16 H1 = __float2bfloat16(bxv[e + 1]);
                __nv_bfloat16 L0 = __float2bfloat16(bxv[e]     - __bfloat162float(H0));
                __nv_bfloat16 L1 = __float2bfloat16(bxv[e + 1] - __bfloat162float(H1));
                *(__nv_bfloat162*)&sBh[idx] = __nv_bfloat162(H0, H1);
                *(__nv_bfloat162*)&sBl[idx] = __nv_bfloat162(L0, L1);
            }
        }
        __syncthreads();

        // ---- tensor-core compute: 2 k16 steps, 3 precision terms each ----
#pragma unroll
        for (int ks = 0; ks < 2; ks++) {
            uint32_t kb = (uint32_t)(ks * 16 * 2);   // byte offset within row
            uint32_t ah[4][4], bb[2][4];

            // term 1: Ah * Bh
#pragma unroll
            for (int mi = 0; mi < 4; mi++) ldsm_x4(ah[mi], bAh + aAoff[mi] + kb);
#pragma unroll
            for (int p = 0; p < 2; p++)    ldsm_x4(bb[p], bBh + aBoff[p] + kb);
#pragma unroll
            for (int mi = 0; mi < 4; mi++)
#pragma unroll
                for (int ni = 0; ni < 4; ni++)
                    mma16816(acc[mi][ni], ah[mi], &bb[ni >> 1][(ni & 1) * 2]);

            // term 2: Ah * Bl
#pragma unroll
            for (int p = 0; p < 2; p++)    ldsm_x4(bb[p], bBl + aBoff[p] + kb);
#pragma unroll
            for (int mi = 0; mi < 4; mi++)
#pragma unroll
                for (int ni = 0; ni < 4; ni++)
                    mma16816(acc[mi][ni], ah[mi], &bb[ni >> 1][(ni & 1) * 2]);

            // term 3: Al * Bh
#pragma unroll
            for (int mi = 0; mi < 4; mi++) ldsm_x4(ah[mi], bAl + aAoff[mi] + kb);
#pragma unroll
            for (int p = 0; p < 2; p++)    ldsm_x4(bb[p], bBh + aBoff[p] + kb);
#pragma unroll
            for (int mi = 0; mi < 4; mi++)
#pragma unroll
                for (int ni = 0; ni < 4; ni++)
                    mma16816(acc[mi][ni], ah[mi], &bb[ni >> 1][(ni & 1) * 2]);
        }
        __syncthreads();
    }

    // ---- epilogue: fragment layout c0,c1 @ (r, 2c), c2,c3 @ (r+8, 2c) ----
#pragma unroll
    for (int mi = 0; mi < 4; mi++) {
        int r0 = by * BM + wm + mi * 16 + (lane >> 2);
#pragma unroll
        for (int ni = 0; ni < 4; ni++) {
            int cc = bx * BN + wn + ni * 8 + (lane & 3) * 2;
            float2 v0 = make_float2(acc[mi][ni][0], acc[mi][ni][1]);
            float2 v1 = make_float2(acc[mi][ni][2], acc[mi][ni][3]);
            *(float2*)&C[(size_t)r0 * N + cc]       = v0;
            *(float2*)&C[(size_t)(r0 + 8) * N + cc] = v1;
        }
    }
}

// Fused QKV projection: grid.z selects (Wq->g_Q, Wk->g_K, Wv->g_V).
__global__ __launch_bounds__(256, 2)
void qkv_proj_tc(const float* __restrict__ x,
                 const float* __restrict__ Wq,
                 const float* __restrict__ Wk,
                 const float* __restrict__ Wv)
{
    const float* W;
    float* C;
    switch (blockIdx.z) {
        case 0:  W = Wq; C = g_Q; break;
        case 1:  W = Wk; C = g_K; break;
        default: W = Wv; C = g_V; break;
    }
    gemm_tc_body(x, W, C, blockIdx.x, blockIdx.y);
}

__global__ __launch_bounds__(256, 2)
void out_proj_tc(const float* __restrict__ Wo, float* __restrict__ out)
{
    gemm_tc_body(g_ctx, Wo, out, blockIdx.x, blockIdx.y);
}

// ----------------------------------------------------------------------------
// RoPE (interleaved pairs), fp64 angles (positions up to 2047 rad).
// ----------------------------------------------------------------------------
__global__ void rope_kernel(const int* __restrict__ pos)
{
    int idx = blockIdx.x * blockDim.x + threadIdx.x;
    const int total = M_ROWS * NUM_HEADS * HALF_DK;
    if (idx >= total) return;

    int i = idx % HALF_DK;
    int h = (idx / HALF_DK) % NUM_HEADS;
    int m = idx / (HALF_DK * NUM_HEADS);

    double p = (double)pos[m];
    double inv = pow(10000.0, -(double)i / 64.0);
    double ang = p * inv;
    float c = (float)cos(ang);
    float s = (float)sin(ang);

    size_t base = (size_t)m * D_MODEL + h * D_K + 2 * i;

    float q1 = g_Q[base], q2 = g_Q[base + 1];
    g_Q[base]     = q1 * c - q2 * s;
    g_Q[base + 1] = q1 * s + q2 * c;

    float k1 = g_K[base], k2 = g_K[base + 1];
    g_K[base]     = k1 * c - k2 * s;
    g_K[base + 1] = k1 * s + k2 * c;
}

// ----------------------------------------------------------------------------
// Flash attention, fp32, causal. Br=Bc=64, 256 threads.
// ----------------------------------------------------------------------------
#define KS_STRIDE 132
#define PS_STRIDE 65
#define ATTN_SMEM_FLOATS (64*128 + 64*KS_STRIDE + 64*128 + 64*PS_STRIDE)
#define ATTN_SMEM_BYTES  (ATTN_SMEM_FLOATS * 4)

__global__ __launch_bounds__(256, 1)
void attn_kernel()
{
    extern __shared__ float sm[];
    float* Qs = sm;
    float* Ks = Qs + 64 * 128;
    float* Vs = Ks + 64 * KS_STRIDE;
    float* Ps = Vs + 64 * 128;

    const int qt  = blockIdx.x;
    const int bh  = blockIdx.y;
    const int b   = bh >> 4;
    const int h   = bh & 15;
    const int tid = threadIdx.x;
    const int tr  = tid >> 4;
    const int tc  = tid & 15;

    const float scale = 0.08838834764831845f;

    const size_t rowst = D_MODEL;
    const float* Qg = g_Q + ((size_t)b * SEQ + qt * 64) * rowst + h * D_K;

    for (int t = tid; t < 64 * 32; t += 256) {
        int r = t >> 5, c4 = (t & 31) * 4;
        float4 v = *(const float4*)(Qg + (size_t)r * rowst + c4);
        v.x *= scale; v.y *= scale; v.z *= scale; v.w *= scale;
        *(float4*)&Qs[r * 128 + c4] = v;
    }

    float m_i[4], l_i[4], o[4][8];
#pragma unroll
    for (int i = 0; i < 4; i++) {
        m_i[i] = -1e30f; l_i[i] = 0.0f;
#pragma unroll
        for (int c = 0; c < 8; c++) o[i][c] = 0.0f;
    }
    __syncthreads();

    for (int j = 0; j <= qt; j++) {
        const float* Kg = g_K + ((size_t)b * SEQ + j * 64) * rowst + h * D_K;
        const float* Vg = g_V + ((size_t)b * SEQ + j * 64) * rowst + h * D_K;
        for (int t = tid; t < 64 * 32; t += 256) {
            int r = t >> 5, c4 = (t & 31) * 4;
            *(float4*)&Ks[r * KS_STRIDE + c4] = *(const float4*)(Kg + (size_t)r * rowst + c4);
            *(float4*)&Vs[r * 128 + c4]       = *(const float4*)(Vg + (size_t)r * rowst + c4);
        }
        __syncthreads();

        float s[4][4];
#pragma unroll
        for (int i = 0; i < 4; i++)
#pragma unroll
            for (int jj = 0; jj < 4; jj++) s[i][jj] = 0.0f;

        for (int d = 0; d < 128; d++) {
            float qv[4], kv[4];
#pragma unroll
            for (int i = 0; i < 4; i++)  qv[i]  = Qs[(tr * 4 + i) * 128 + d];
#pragma unroll
            for (int jj = 0; jj < 4; jj++) kv[jj] = Ks[(tc + 16 * jj) * KS_STRIDE + d];
#pragma unroll
            for (int i = 0; i < 4; i++)
#pragma unroll
                for (int jj = 0; jj < 4; jj++)
                    s[i][jj] = fmaf(qv[i], kv[jj], s[i][jj]);
        }

        if (j == qt) {
#pragma unroll
            for (int i = 0; i < 4; i++) {
                int r = tr * 4 + i;
#pragma unroll
                for (int jj = 0; jj < 4; jj++) {
                    int kk = tc + 16 * jj;
                    if (kk > r) s[i][jj] = -1e30f;
                }
            }
        }

#pragma unroll
        for (int i = 0; i < 4; i++) {
            float mloc = s[i][0];
#pragma unroll
            for (int jj = 1; jj < 4; jj++) mloc = fmaxf(mloc, s[i][jj]);
#pragma unroll
            for (int off = 8; off > 0; off >>= 1)
                mloc = fmaxf(mloc, __shfl_xor_sync(0xffffffffu, mloc, off, 16));
            float mnew  = fmaxf(m_i[i], mloc);
            float alpha = __expf(m_i[i] - mnew);

            float psum = 0.0f;
#pragma unroll
            for (int jj = 0; jj < 4; jj++) {
                float p = __expf(s[i][jj] - mnew);
                Ps[(tr * 4 + i) * PS_STRIDE + tc + 16 * jj] = p;
                psum += p;
            }
#pragma unroll
            for (int off = 8; off > 0; off >>= 1)
                psum += __shfl_xor_sync(0xffffffffu, psum, off, 16);

            l_i[i] = l_i[i] * alpha + psum;
            m_i[i] = mnew;
#pragma unroll
            for (int c = 0; c < 8; c++) o[i][c] *= alpha;
        }
        __syncthreads();

        for (int kk = 0; kk < 64; kk++) {
            float pv[4];
#pragma unroll
            for (int i = 0; i < 4; i++) pv[i] = Ps[(tr * 4 + i) * PS_STRIDE + kk];
            float4 v0 = *(const float4*)&Vs[kk * 128 + tc * 8];
            float4 v1 = *(const float4*)&Vs[kk * 128 + tc * 8 + 4];
#pragma unroll
            for (int i = 0; i < 4; i++) {
                o[i][0] = fmaf(pv[i], v0.x, o[i][0]);
                o[i][1] = fmaf(pv[i], v0.y, o[i][1]);
                o[i][2] = fmaf(pv[i], v0.z, o[i][2]);
                o[i][3] = fmaf(pv[i], v0.w, o[i][3]);
                o[i][4] = fmaf(pv[i], v1.x, o[i][4]);
                o[i][5] = fmaf(pv[i], v1.y, o[i][5]);
                o[i][6] = fmaf(pv[i], v1.z, o[i][6]);
                o[i][7] = fmaf(pv[i], v1.w, o[i][7]);
            }
        }
        __syncthreads();
    }

    float* Og = g_ctx + ((size_t)b * SEQ + qt * 64) * rowst + h * D_K;
#pragma unroll
    for (int i = 0; i < 4; i++) {
        int r = tr * 4 + i;
        float inv_l = 1.0f / l_i[i];
        float4 w0, w1;
        w0.x = o[i][0] * inv_l; w0.y = o[i][1] * inv_l;
        w0.z = o[i][2] * inv_l; w0.w = o[i][3] * inv_l;
        w1.x = o[i][4] * inv_l; w1.y = o[i][5] * inv_l;
        w1.z = o[i][6] * inv_l; w1.w = o[i][7] * inv_l;
        *(float4*)(Og + (size_t)r * rowst + tc * 8)     = w0;
        *(float4*)(Og + (size_t)r * rowst + tc * 8 + 4) = w1;
    }
}

// ----------------------------------------------------------------------------
// Launcher
// ----------------------------------------------------------------------------
extern "C" void kernel_launch(void* const* d_in, const int* in_sizes, int n_in,
                              void* d_out, int out_size)
{
    const float* x   = (const float*)d_in[0];
    const int*   pos = (const int*)d_in[1];
    const float* Wq  = (const float*)d_in[2];
    const float* Wk  = (const float*)d_in[3];
    const float* Wv  = (const float*)d_in[4];
    const float* Wo  = (const float*)d_in[5];
    float* out = (float*)d_out;

    dim3 gthr(256);
    dim3 qkv_grid(D_MODEL / BN, M_ROWS / BM, 3);     // (16, 32, 3)
    qkv_proj_tc<<<qkv_grid, gthr>>>(x, Wq, Wk, Wv);

    {
        int total = M_ROWS * NUM_HEADS * HALF_DK;
        rope_kernel<<<(total + 255) / 256, 256>>>(pos);
    }

    cudaFuncSetAttribute(attn_kernel, cudaFuncAttributeMaxDynamicSharedMemorySize,
                         ATTN_SMEM_BYTES);
    attn_kernel<<<dim3(SEQ / 64, BATCH * NUM_HEADS), 256, ATTN_SMEM_BYTES>>>();

    dim3 ogrid(D_MODEL / BN, M_ROWS / BM);           // (16, 32)
    out_proj_tc<<<ogrid, gthr>>>(Wo, out);
}

// round 7
// speedup vs baseline: 3.0180x; 1.8507x over previous
#include <cuda_runtime.h>
#include <cuda_bf16.h>
#include <math.h>
#include <stdint.h>

// ----------------------------------------------------------------------------
// Problem constants
// ----------------------------------------------------------------------------
#define D_MODEL   2048
#define NUM_HEADS 16
#define D_K       128
#define HALF_DK   64
#define BATCH     2
#define SEQ       2048
#define M_ROWS    (BATCH * SEQ)          // 4096
#define NX (M_ROWS * D_MODEL)            // 8,388,608 elems (activation-sized)
#define NW (D_MODEL * D_MODEL)           // 4,194,304 elems (weight-sized)

typedef __nv_bfloat16  bf16;
typedef __nv_bfloat162 bf162;

// ----------------------------------------------------------------------------
// Scratch (device globals). hi at [0, N), lo at [N, 2N).
// Referenced ONLY from device code — never passed from host.
// ----------------------------------------------------------------------------
__device__ float g_Qf[NX];
__device__ float g_Kf[NX];

__device__ bf16 g_x [2 * NX];
__device__ bf16 g_Wq[2 * NW], g_Wk[2 * NW], g_Wv[2 * NW], g_Wo[2 * NW];
__device__ bf16 g_Q [2 * NX], g_K [2 * NX], g_V [2 * NX], g_ctx[2 * NX];

// ----------------------------------------------------------------------------
// PTX helpers
// ----------------------------------------------------------------------------
__device__ __forceinline__ void ldsm_x4(uint32_t* r, uint32_t addr) {
    asm volatile("ldmatrix.sync.aligned.m8n8.x4.shared.b16 {%0,%1,%2,%3}, [%4];"
                 : "=r"(r[0]), "=r"(r[1]), "=r"(r[2]), "=r"(r[3]) : "r"(addr));
}
__device__ __forceinline__ void ldsm_x4_t(uint32_t* r, uint32_t addr) {
    asm volatile("ldmatrix.sync.aligned.m8n8.x4.trans.shared.b16 {%0,%1,%2,%3}, [%4];"
                 : "=r"(r[0]), "=r"(r[1]), "=r"(r[2]), "=r"(r[3]) : "r"(addr));
}
__device__ __forceinline__ void mma16816(float* c, const uint32_t* a, const uint32_t* b) {
    asm volatile("mma.sync.aligned.m16n8k16.row.col.f32.bf16.bf16.f32 "
                 "{%0,%1,%2,%3},{%4,%5,%6,%7},{%8,%9},{%0,%1,%2,%3};"
                 : "+f"(c[0]), "+f"(c[1]), "+f"(c[2]), "+f"(c[3])
                 : "r"(a[0]), "r"(a[1]), "r"(a[2]), "r"(a[3]), "r"(b[0]), "r"(b[1]));
}
__device__ __forceinline__ void cp16(uint32_t dst, const void* src) {
    asm volatile("cp.async.ca.shared.global [%0], [%1], 16;" :: "r"(dst), "l"(src));
}
__device__ __forceinline__ void cp_commit() {
    asm volatile("cp.async.commit_group;");
}
__device__ __forceinline__ void cp_wait1() {
    asm volatile("cp.async.wait_group 1;");
}

// ----------------------------------------------------------------------------
// Split all 5 input tensors fp32 -> (hi, lo) bf16 in one launch.
// blockIdx.y selects tensor; destination globals chosen in DEVICE code.
// ----------------------------------------------------------------------------
__global__ void split_all(const float* __restrict__ x,
                          const float* __restrict__ Wq,
                          const float* __restrict__ Wk,
                          const float* __restrict__ Wv,
                          const float* __restrict__ Wo)
{
    const float* src;
    bf16 *h, *l;
    int n4;
    switch (blockIdx.y) {
        case 0:  src = x;  h = g_x;  l = g_x  + NX; n4 = NX / 4; break;
        case 1:  src = Wq; h = g_Wq; l = g_Wq + NW; n4 = NW / 4; break;
        case 2:  src = Wk; h = g_Wk; l = g_Wk + NW; n4 = NW / 4; break;
        case 3:  src = Wv; h = g_Wv; l = g_Wv + NW; n4 = NW / 4; break;
        default: src = Wo; h = g_Wo; l = g_Wo + NW; n4 = NW / 4; break;
    }
    int i = blockIdx.x * blockDim.x + threadIdx.x;
    if (i >= n4) return;
    float4 v = ((const float4*)src)[i];
    float vv[4] = {v.x, v.y, v.z, v.w};
    bf16 hh[4], ll[4];
#pragma unroll
    for (int e = 0; e < 4; e++) {
        hh[e] = __float2bfloat16(vv[e]);
        ll[e] = __float2bfloat16(vv[e] - __bfloat162float(hh[e]));
    }
    ((bf162*)h)[i * 2]     = bf162(hh[0], hh[1]);
    ((bf162*)h)[i * 2 + 1] = bf162(hh[2], hh[3]);
    ((bf162*)l)[i * 2]     = bf162(ll[0], ll[1]);
    ((bf162*)l)[i * 2 + 1] = bf162(ll[2], ll[3]);
}

// ----------------------------------------------------------------------------
// Tensor-core GEMM (bf16 hi/lo): C[M,N] = A * B^T, 3-term split.
// 128x128x32 tiles, 256 threads, 2-stage cp.async pipeline.
// lo planes at compile-time offsets OFFA/OFFB from hi base pointers.
// ----------------------------------------------------------------------------
#define BM 128
#define BN 128
#define BKT 32
#define SSTR 40
#define ARR_ELEMS (BM * SSTR)           // 5120
#define STAGE_ELEMS (4 * ARR_ELEMS)     // 20480
#define GEMM_SMEM_BYTES (2 * STAGE_ELEMS * 2)   // 81920

template<int SPLIT_OUT, int OFFA, int OFFB>
__device__ __forceinline__
void gemm3_body(const bf16* __restrict__ A, const bf16* __restrict__ B,
                float* __restrict__ C, bf16* __restrict__ Ch,
                int bx, int by)
{
    extern __shared__ bf16 smem[];
    const int tid  = threadIdx.x;
    const int lane = tid & 31;
    const int wid  = tid >> 5;
    const int wm   = (wid >> 2) * 64;
    const int wn   = (wid & 3) * 32;
    const int K = D_MODEL, N = D_MODEL;

    float acc[4][4][4];
#pragma unroll
    for (int mi = 0; mi < 4; mi++)
#pragma unroll
        for (int ni = 0; ni < 4; ni++)
#pragma unroll
            for (int e = 0; e < 4; e++) acc[mi][ni][e] = 0.0f;

    const int lrow = tid >> 1;
    const int lcol = (tid & 1) * 16;
    const bf16* gA = A + (size_t)(by * BM + lrow) * K + lcol;   // hi; lo at +OFFA
    const bf16* gB = B + (size_t)(bx * BN + lrow) * K + lcol;   // hi; lo at +OFFB

    uint32_t sbase = (uint32_t)__cvta_generic_to_shared(smem);
    uint32_t ldst  = (uint32_t)((lrow * SSTR + lcol) * 2);

    uint32_t aoff[4];
#pragma unroll
    for (int mi = 0; mi < 4; mi++)
        aoff[mi] = (uint32_t)(((wm + mi * 16 + (lane & 15)) * SSTR + (lane >> 4) * 8) * 2);
    uint32_t boff[2];
#pragma unroll
    for (int p = 0; p < 2; p++) {
        int g = lane >> 3;
        boff[p] = (uint32_t)(((wn + p * 16 + (g >> 1) * 8 + (lane & 7)) * SSTR + (g & 1) * 8) * 2);
    }

    const int NT = K / BKT;   // 64

    {   // prefetch stage 0
        uint32_t so = sbase;
        cp16(so + ldst,                      gA);
        cp16(so + ldst + 16,                 gA + 8);
        cp16(so + ARR_ELEMS * 2 + ldst,      gA + OFFA);
        cp16(so + ARR_ELEMS * 2 + ldst + 16, gA + OFFA + 8);
        cp16(so + ARR_ELEMS * 4 + ldst,      gB);
        cp16(so + ARR_ELEMS * 4 + ldst + 16, gB + 8);
        cp16(so + ARR_ELEMS * 6 + ldst,      gB + OFFB);
        cp16(so + ARR_ELEMS * 6 + ldst + 16, gB + OFFB + 8);
        cp_commit();
    }

    for (int kt = 0; kt < NT; kt++) {
        int cur = kt & 1;
        if (kt + 1 < NT) {
            uint32_t so = sbase + (uint32_t)(((kt + 1) & 1) * STAGE_ELEMS * 2);
            int kof = (kt + 1) * BKT;
            cp16(so + ldst,                      gA + kof);
            cp16(so + ldst + 16,                 gA + kof + 8);
            cp16(so + ARR_ELEMS * 2 + ldst,      gA + OFFA + kof);
            cp16(so + ARR_ELEMS * 2 + ldst + 16, gA + OFFA + kof + 8);
            cp16(so + ARR_ELEMS * 4 + ldst,      gB + kof);
            cp16(so + ARR_ELEMS * 4 + ldst + 16, gB + kof + 8);
            cp16(so + ARR_ELEMS * 6 + ldst,      gB + OFFB + kof);
            cp16(so + ARR_ELEMS * 6 + ldst + 16, gB + OFFB + kof + 8);
        }
        cp_commit();
        cp_wait1();
        __syncthreads();

        uint32_t sAh = sbase + (uint32_t)(cur * STAGE_ELEMS * 2);
        uint32_t sAl = sAh + ARR_ELEMS * 2;
        uint32_t sBh = sAh + ARR_ELEMS * 4;
        uint32_t sBl = sAh + ARR_ELEMS * 6;

#pragma unroll
        for (int ks = 0; ks < 2; ks++) {
            uint32_t kb = (uint32_t)(ks * 32);
            uint32_t ah[4][4], bb[2][4];

            // t1: Ah*Bh
#pragma unroll
            for (int mi = 0; mi < 4; mi++) ldsm_x4(ah[mi], sAh + aoff[mi] + kb);
#pragma unroll
            for (int p = 0; p < 2; p++)    ldsm_x4(bb[p], sBh + boff[p] + kb);
#pragma unroll
            for (int mi = 0; mi < 4; mi++)
#pragma unroll
                for (int ni = 0; ni < 4; ni++)
                    mma16816(acc[mi][ni], ah[mi], &bb[ni >> 1][(ni & 1) * 2]);

            // t2: Ah*Bl (reuse ah)
#pragma unroll
            for (int p = 0; p < 2; p++)    ldsm_x4(bb[p], sBl + boff[p] + kb);
#pragma unroll
            for (int mi = 0; mi < 4; mi++)
#pragma unroll
                for (int ni = 0; ni < 4; ni++)
                    mma16816(acc[mi][ni], ah[mi], &bb[ni >> 1][(ni & 1) * 2]);

            // t3: Al*Bh
#pragma unroll
            for (int mi = 0; mi < 4; mi++) ldsm_x4(ah[mi], sAl + aoff[mi] + kb);
#pragma unroll
            for (int p = 0; p < 2; p++)    ldsm_x4(bb[p], sBh + boff[p] + kb);
#pragma unroll
            for (int mi = 0; mi < 4; mi++)
#pragma unroll
                for (int ni = 0; ni < 4; ni++)
                    mma16816(acc[mi][ni], ah[mi], &bb[ni >> 1][(ni & 1) * 2]);
        }
        __syncthreads();
    }

#pragma unroll
    for (int mi = 0; mi < 4; mi++) {
        int r0 = by * BM + wm + mi * 16 + (lane >> 2);
#pragma unroll
        for (int ni = 0; ni < 4; ni++) {
            int cc = bx * BN + wn + ni * 8 + (lane & 3) * 2;
            if (SPLIT_OUT) {
                bf16* Cl = Ch + NX;   // split outputs are activation-sized
                float v0 = acc[mi][ni][0], v1 = acc[mi][ni][1];
                bf162 h0 = __floats2bfloat162_rn(v0, v1);
                bf162 l0 = __floats2bfloat162_rn(v0 - __bfloat162float(h0.x),
                                                 v1 - __bfloat162float(h0.y));
                *(bf162*)&Ch[(size_t)r0 * N + cc] = h0;
                *(bf162*)&Cl[(size_t)r0 * N + cc] = l0;
                float v2 = acc[mi][ni][2], v3 = acc[mi][ni][3];
                bf162 h1 = __floats2bfloat162_rn(v2, v3);
                bf162 l1 = __floats2bfloat162_rn(v2 - __bfloat162float(h1.x),
                                                 v3 - __bfloat162float(h1.y));
                *(bf162*)&Ch[(size_t)(r0 + 8) * N + cc] = h1;
                *(bf162*)&Cl[(size_t)(r0 + 8) * N + cc] = l1;
            } else {
                *(float2*)&C[(size_t)r0 * N + cc] =
                    make_float2(acc[mi][ni][0], acc[mi][ni][1]);
                *(float2*)&C[(size_t)(r0 + 8) * N + cc] =
                    make_float2(acc[mi][ni][2], acc[mi][ni][3]);
            }
        }
    }
}

__global__ __launch_bounds__(256, 2)
void qkv_tc()
{
    if (blockIdx.z == 0)
        gemm3_body<0, NX, NW>(g_x, g_Wq, g_Qf, nullptr, blockIdx.x, blockIdx.y);
    else if (blockIdx.z == 1)
        gemm3_body<0, NX, NW>(g_x, g_Wk, g_Kf, nullptr, blockIdx.x, blockIdx.y);
    else
        gemm3_body<1, NX, NW>(g_x, g_Wv, nullptr, g_V, blockIdx.x, blockIdx.y);
}

__global__ __launch_bounds__(256, 2)
void out_tc(float* __restrict__ out)
{
    gemm3_body<0, NX, NW>(g_ctx, g_Wo, out, nullptr, blockIdx.x, blockIdx.y);
}

// ----------------------------------------------------------------------------
// RoPE (fp64 angles) + hi/lo split; Q pre-scaled by 1/sqrt(d_k).
// ----------------------------------------------------------------------------
__global__ void rope_split_kernel(const int* __restrict__ pos)
{
    int idx = blockIdx.x * blockDim.x + threadIdx.x;
    const int total = M_ROWS * NUM_HEADS * HALF_DK;
    if (idx >= total) return;

    int i = idx % HALF_DK;
    int h = (idx / HALF_DK) % NUM_HEADS;
    int m = idx / (HALF_DK * NUM_HEADS);

    double p = (double)pos[m];
    double inv = pow(10000.0, -(double)i / 64.0);
    double ang = p * inv;
    float c = (float)cos(ang);
    float s = (float)sin(ang);
    const float qscale = 0.08838834764831845f;   // 1/sqrt(128)

    size_t base = (size_t)m * D_MODEL + h * D_K + 2 * i;

    float q1 = g_Qf[base], q2 = g_Qf[base + 1];
    float qr1 = (q1 * c - q2 * s) * qscale;
    float qr2 = (q1 * s + q2 * c) * qscale;
    bf162 qh = __floats2bfloat162_rn(qr1, qr2);
    bf162 ql = __floats2bfloat162_rn(qr1 - __bfloat162float(qh.x),
                                     qr2 - __bfloat162float(qh.y));
    *(bf162*)&g_Q[base]      = qh;
    *(bf162*)&g_Q[NX + base] = ql;

    float k1 = g_Kf[base], k2 = g_Kf[base + 1];
    float kr1 = k1 * c - k2 * s;
    float kr2 = k1 * s + k2 * c;
    bf162 kh = __floats2bfloat162_rn(kr1, kr2);
    bf162 kl = __floats2bfloat162_rn(kr1 - __bfloat162float(kh.x),
                                     kr2 - __bfloat162float(kh.y));
    *(bf162*)&g_K[base]      = kh;
    *(bf162*)&g_K[NX + base] = kl;
}

// ----------------------------------------------------------------------------
// Tensor-core flash attention, causal. Br=128, Bc=64, 256 threads (8 warps,
// 16 q-rows each). 3-term split-bf16 QK^T and PV; P hi/lo built per kb.
// smem: Qh/Ql[128][136] + Kh/Kl/Vh/Vl[64][136] bf16 = 139,264 B.
// ----------------------------------------------------------------------------
#define ASTR 136
#define SQH 0
#define SQL (128 * ASTR)
#define SKH (2 * 128 * ASTR)
#define SKL (SKH + 64 * ASTR)
#define SVH (SKL + 64 * ASTR)
#define SVL (SVH + 64 * ASTR)
#define ATTN_SMEM_BYTES ((2 * 128 * ASTR + 4 * 64 * ASTR) * 2)

__global__ __launch_bounds__(256, 1)
void attn_tc()
{
    extern __shared__ bf16 sm[];
    const int tid  = threadIdx.x;
    const int lane = tid & 31;
    const int w    = tid >> 5;
    const int qt   = (int)gridDim.x - 1 - (int)blockIdx.x;   // big tiles first
    const int bh   = blockIdx.y;
    const int b    = bh >> 4;
    const int h    = bh & 15;
    const int qrow0 = qt * 128;
    const int wrow  = w * 16;

    uint32_t sbase = (uint32_t)__cvta_generic_to_shared(sm);

    // ---- load Q tile (hi/lo) ----
    {
        int row = tid >> 1, colb = (tid & 1) * 64;
        size_t gq = (size_t)(b * SEQ + qrow0 + row) * D_MODEL + h * D_K + colb;
#pragma unroll
        for (int cc = 0; cc < 8; cc++) {
            *(uint4*)&sm[SQH + row * ASTR + colb + cc * 8] = *(const uint4*)(g_Q + gq + cc * 8);
            *(uint4*)&sm[SQL + row * ASTR + colb + cc * 8] = *(const uint4*)(g_Q + NX + gq + cc * 8);
        }
    }

    float O[16][4];
#pragma unroll
    for (int nt = 0; nt < 16; nt++)
#pragma unroll
        for (int e = 0; e < 4; e++) O[nt][e] = 0.0f;
    float m_i[2] = {-1e30f, -1e30f};
    float l_i[2] = {0.0f, 0.0f};

    uint32_t aoff = (uint32_t)(((wrow + (lane & 15)) * ASTR + (lane >> 4) * 8) * 2);
    uint32_t boff[4];
#pragma unroll
    for (int p = 0; p < 4; p++) {
        int g = lane >> 3;
        boff[p] = (uint32_t)(((p * 16 + (g >> 1) * 8 + (lane & 7)) * ASTR + (g & 1) * 8) * 2);
    }
    int vrow = ((lane >> 3) & 1) * 8 + (lane & 7);
    int vcol = (lane >> 4) * 8;

    const int njt = 2 * qt + 2;
    for (int j = 0; j < njt; j++) {
        // ---- load K/V tile (hi/lo) ----
        {
            int row = tid >> 2, colb = (tid & 3) * 32;
            size_t gb = (size_t)(b * SEQ + j * 64 + row) * D_MODEL + h * D_K + colb;
#pragma unroll
            for (int cc = 0; cc < 4; cc++) {
                *(uint4*)&sm[SKH + row * ASTR + colb + cc * 8] = *(const uint4*)(g_K + gb + cc * 8);
                *(uint4*)&sm[SKL + row * ASTR + colb + cc * 8] = *(const uint4*)(g_K + NX + gb + cc * 8);
                *(uint4*)&sm[SVH + row * ASTR + colb + cc * 8] = *(const uint4*)(g_V + gb + cc * 8);
                *(uint4*)&sm[SVL + row * ASTR + colb + cc * 8] = *(const uint4*)(g_V + NX + gb + cc * 8);
            }
        }
        __syncthreads();

        bool active = (j * 64 <= qrow0 + wrow + 15);
        if (active) {
            // ---- S = Q K^T (3-term) ----
            float S[8][4];
#pragma unroll
            for (int t = 0; t < 8; t++)
#pragma unroll
                for (int e = 0; e < 4; e++) S[t][e] = 0.0f;

#pragma unroll
            for (int ks = 0; ks < 8; ks++) {
                uint32_t kb = (uint32_t)(ks * 32);
                uint32_t aq[4], bb[4][4];
                // t1: Qh*Kh
                ldsm_x4(aq, sbase + SQH * 2 + aoff + kb);
#pragma unroll
                for (int p = 0; p < 4; p++) ldsm_x4(bb[p], sbase + SKH * 2 + boff[p] + kb);
#pragma unroll
                for (int t = 0; t < 8; t++) mma16816(S[t], aq, &bb[t >> 1][(t & 1) * 2]);
                // t2: Qh*Kl
#pragma unroll
                for (int p = 0; p < 4; p++) ldsm_x4(bb[p], sbase + SKL * 2 + boff[p] + kb);
#pragma unroll
                for (int t = 0; t < 8; t++) mma16816(S[t], aq, &bb[t >> 1][(t & 1) * 2]);
                // t3: Ql*Kh
                ldsm_x4(aq, sbase + SQL * 2 + aoff + kb);
#pragma unroll
                for (int p = 0; p < 4; p++) ldsm_x4(bb[p], sbase + SKH * 2 + boff[p] + kb);
#pragma unroll
                for (int t = 0; t < 8; t++) mma16816(S[t], aq, &bb[t >> 1][(t & 1) * 2]);
            }

            // ---- causal mask ----
            int grow0 = qrow0 + wrow + (lane >> 2);
            int grow1 = grow0 + 8;
            if (j * 64 + 63 > qrow0 + wrow) {
#pragma unroll
                for (int t = 0; t < 8; t++) {
                    int c0 = j * 64 + t * 8 + 2 * (lane & 3);
                    if (c0     > grow0) S[t][0] = -1e30f;
                    if (c0 + 1 > grow0) S[t][1] = -1e30f;
                    if (c0     > grow1) S[t][2] = -1e30f;
                    if (c0 + 1 > grow1) S[t][3] = -1e30f;
                }
            }

            // ---- online softmax ----
            float mx0 = -1e30f, mx1 = -1e30f;
#pragma unroll
            for (int t = 0; t < 8; t++) {
                mx0 = fmaxf(mx0, fmaxf(S[t][0], S[t][1]));
                mx1 = fmaxf(mx1, fmaxf(S[t][2], S[t][3]));
            }
            mx0 = fmaxf(mx0, __shfl_xor_sync(0xffffffffu, mx0, 1));
            mx0 = fmaxf(mx0, __shfl_xor_sync(0xffffffffu, mx0, 2));
            mx1 = fmaxf(mx1, __shfl_xor_sync(0xffffffffu, mx1, 1));
            mx1 = fmaxf(mx1, __shfl_xor_sync(0xffffffffu, mx1, 2));

            float mn0 = fmaxf(m_i[0], mx0), mn1 = fmaxf(m_i[1], mx1);
            float al0 = __expf(m_i[0] - mn0), al1 = __expf(m_i[1] - mn1);
            m_i[0] = mn0; m_i[1] = mn1;

            float sum0 = 0.0f, sum1 = 0.0f;
#pragma unroll
            for (int t = 0; t < 8; t++) {
                S[t][0] = __expf(S[t][0] - mn0);
                S[t][1] = __expf(S[t][1] - mn0);
                S[t][2] = __expf(S[t][2] - mn1);
                S[t][3] = __expf(S[t][3] - mn1);
                sum0 += S[t][0] + S[t][1];
                sum1 += S[t][2] + S[t][3];
            }
            sum0 += __shfl_xor_sync(0xffffffffu, sum0, 1);
            sum0 += __shfl_xor_sync(0xffffffffu, sum0, 2);
            sum1 += __shfl_xor_sync(0xffffffffu, sum1, 1);
            sum1 += __shfl_xor_sync(0xffffffffu, sum1, 2);
            l_i[0] = l_i[0] * al0 + sum0;
            l_i[1] = l_i[1] * al1 + sum1;

#pragma unroll
            for (int nt = 0; nt < 16; nt++) {
                O[nt][0] *= al0; O[nt][1] *= al0;
                O[nt][2] *= al1; O[nt][3] *= al1;
            }

            // ---- O += P V (3-term; P hi/lo fragments built per kb) ----
#pragma unroll
            for (int kb = 0; kb < 4; kb++) {
                uint32_t ph[4], pl[4];
#pragma unroll
                for (int u = 0; u < 2; u++) {
                    int t = 2 * kb + u;
                    bf162 h01 = __floats2bfloat162_rn(S[t][0], S[t][1]);
                    bf162 l01 = __floats2bfloat162_rn(S[t][0] - __bfloat162float(h01.x),
                                                      S[t][1] - __bfloat162float(h01.y));
                    bf162 h23 = __floats2bfloat162_rn(S[t][2], S[t][3]);
                    bf162 l23 = __floats2bfloat162_rn(S[t][2] - __bfloat162float(h23.x),
                                                      S[t][3] - __bfloat162float(h23.y));
                    ph[2 * u]     = *(uint32_t*)&h01;
                    pl[2 * u]     = *(uint32_t*)&l01;
                    ph[2 * u + 1] = *(uint32_t*)&h23;
                    pl[2 * u + 1] = *(uint32_t*)&l23;
                }
#pragma unroll
                for (int half = 0; half < 2; half++) {
                    uint32_t vb[4][4];
#pragma unroll
                    for (int i = 0; i < 4; i++)
                        ldsm_x4_t(vb[i], sbase + SVH * 2 +
                                  (uint32_t)(((kb * 16 + vrow) * ASTR +
                                              (half * 4 + i) * 16 + vcol) * 2));
#pragma unroll
                    for (int nt = 0; nt < 8; nt++)
                        mma16816(O[half * 8 + nt], ph, &vb[nt >> 1][(nt & 1) * 2]);
#pragma unroll
                    for (int nt = 0; nt < 8; nt++)
                        mma16816(O[half * 8 + nt], pl, &vb[nt >> 1][(nt & 1) * 2]);
#pragma unroll
                    for (int i = 0; i < 4; i++)
                        ldsm_x4_t(vb[i], sbase + SVL * 2 +
                                  (uint32_t)(((kb * 16 + vrow) * ASTR +
                                              (half * 4 + i) * 16 + vcol) * 2));
#pragma unroll
                    for (int nt = 0; nt < 8; nt++)
                        mma16816(O[half * 8 + nt], ph, &vb[nt >> 1][(nt & 1) * 2]);
                }
            }
        }
        __syncthreads();
    }

    // ---- epilogue: O /= l, split hi/lo, write ctx ----
    float inv0 = 1.0f / l_i[0], inv1 = 1.0f / l_i[1];
    size_t gr0 = (size_t)(b * SEQ + qrow0 + wrow + (lane >> 2)) * D_MODEL + h * D_K;
    size_t gr1 = gr0 + (size_t)8 * D_MODEL;
#pragma unroll
    for (int nt = 0; nt < 16; nt++) {
        int d0 = nt * 8 + (lane & 3) * 2;
        float v0 = O[nt][0] * inv0, v1 = O[nt][1] * inv0;
        bf162 h0 = __floats2bfloat162_rn(v0, v1);
        bf162 l0 = __floats2bfloat162_rn(v0 - __bfloat162float(h0.x),
                                         v1 - __bfloat162float(h0.y));
        *(bf162*)&g_ctx[gr0 + d0]      = h0;
        *(bf162*)&g_ctx[NX + gr0 + d0] = l0;
        float v2 = O[nt][2] * inv1, v3 = O[nt][3] * inv1;
        bf162 h1 = __floats2bfloat162_rn(v2, v3);
        bf162 l1 = __floats2bfloat162_rn(v2 - __bfloat162float(h1.x),
                                         v3 - __bfloat162float(h1.y));
        *(bf162*)&g_ctx[gr1 + d0]      = h1;
        *(bf162*)&g_ctx[NX + gr1 + d0] = l1;
    }
}

// ----------------------------------------------------------------------------
// Launcher — only harness-provided pointers cross the host/device boundary.
// ----------------------------------------------------------------------------
extern "C" void kernel_launch(void* const* d_in, const int* in_sizes, int n_in,
                              void* d_out, int out_size)
{
    const float* x   = (const float*)d_in[0];
    const int*   pos = (const int*)d_in[1];
    const float* Wq  = (const float*)d_in[2];
    const float* Wk  = (const float*)d_in[3];
    const float* Wv  = (const float*)d_in[4];
    const float* Wo  = (const float*)d_in[5];
    float* out = (float*)d_out;

    // fp32 -> hi/lo bf16 split for all 5 inputs (dest selected in device code)
    {
        int nb = (NX / 4 + 255) / 256;   // largest tensor (x)
        split_all<<<dim3(nb, 5), 256>>>(x, Wq, Wk, Wv, Wo);
    }

    cudaFuncSetAttribute(qkv_tc, cudaFuncAttributeMaxDynamicSharedMemorySize,
                         GEMM_SMEM_BYTES);
    cudaFuncSetAttribute(out_tc, cudaFuncAttributeMaxDynamicSharedMemorySize,
                         GEMM_SMEM_BYTES);
    cudaFuncSetAttribute(attn_tc, cudaFuncAttributeMaxDynamicSharedMemorySize,
                         ATTN_SMEM_BYTES);

    dim3 gthr(256);
    qkv_tc<<<dim3(D_MODEL / BN, M_ROWS / BM, 3), gthr, GEMM_SMEM_BYTES>>>();

    {
        int total = M_ROWS * NUM_HEADS * HALF_DK;
        rope_split_kernel<<<(total + 255) / 256, 256>>>(pos);
    }

    attn_tc<<<dim3(SEQ / 128, BATCH * NUM_HEADS), gthr, ATTN_SMEM_BYTES>>>();

    out_tc<<<dim3(D_MODEL / BN, M_ROWS / BM), gthr, GEMM_SMEM_BYTES>>>(out);
}